// round 5
// baseline (speedup 1.0000x reference)
#include <cuda_runtime.h>
#include <cuda_fp16.h>
#include <cstdint>

#define BB 64
#define TT 1024
#define II 512
#define HH 512
#define MM (BB*TT)              // 65536

#define ALPHA_LO 0.8187307530779818f   // exp(-1/5)
#define ALPHA_HI 0.9607894391523232f   // exp(-1/25)

// Device-global scratch (allocation-guard safe)
__device__ float  g_wx[(size_t)MM * HH];        // 128 MB
__device__ __half g_bh[(size_t)HH * II];        // 512 KB (2048*W) high
__device__ __half g_bl[(size_t)HH * II];        // 512 KB (2048*W) low

// ---------------------------------------------------------------------------
__device__ __forceinline__ uint32_t smem_u32(const void* p) {
    uint32_t a;
    asm("{ .reg .u64 t; cvta.to.shared.u64 t, %1; cvt.u32.u64 %0, t; }" : "=r"(a) : "l"(p));
    return a;
}
__device__ __forceinline__ void cp16(uint32_t dst, const void* src) {
    asm volatile("cp.async.cg.shared.global [%0], [%1], 16;" :: "r"(dst), "l"(src));
}
__device__ __forceinline__ void ldsm_x4(uint32_t* r, uint32_t addr) {
    asm volatile("ldmatrix.sync.aligned.m8n8.x4.shared.b16 {%0,%1,%2,%3}, [%4];"
                 : "=r"(r[0]), "=r"(r[1]), "=r"(r[2]), "=r"(r[3]) : "r"(addr));
}
__device__ __forceinline__ void mma16816(float* c, const uint32_t* a, uint32_t b0, uint32_t b1) {
    asm volatile(
        "mma.sync.aligned.m16n8k16.row.col.f32.f16.f16.f32 "
        "{%0,%1,%2,%3}, {%4,%5,%6,%7}, {%8,%9}, {%0,%1,%2,%3};"
        : "+f"(c[0]), "+f"(c[1]), "+f"(c[2]), "+f"(c[3])
        : "r"(a[0]), "r"(a[1]), "r"(a[2]), "r"(a[3]), "r"(b0), "r"(b1));
}
__device__ __forceinline__ uint32_t h2bits(__half2 h) {
    return *reinterpret_cast<uint32_t*>(&h);
}

// ---------------------------------------------------------------------------
// Prep B: W scaled by 2048, split into fp16 high/low. 4 elems per thread.
// ---------------------------------------------------------------------------
__global__ __launch_bounds__(256)
void prep_b(const float* __restrict__ W) {
    size_t i = ((size_t)blockIdx.x * 256 + threadIdx.x) * 4;
    float4 v = *(const float4*)(W + i);
    float sc[4] = {v.x * 2048.0f, v.y * 2048.0f, v.z * 2048.0f, v.w * 2048.0f};
    __half h[4], l[4];
    #pragma unroll
    for (int j = 0; j < 4; j++) {
        h[j] = __float2half_rn(sc[j]);
        l[j] = __float2half_rn(sc[j] - __half2float(h[j]));
    }
    *(uint2*)(g_bh + i) = *(uint2*)h;
    *(uint2*)(g_bl + i) = *(uint2*)l;
}

// ---------------------------------------------------------------------------
// GEMM: Wx[m,n] = (xh.wh' + xh.wl' + xl.wh') / 2048  (w' = 2048*W)
// CTA 128x128, BK=32, 16 chunks, 8 warps (4m x 2n), warp tile 32x64.
// A: fp32 x staged in smem via cp.async (coalesced, once per CTA); each
//    thread builds its hi/lo fp16 fragments from fp32 smem (stride 40 pad
//    -> conflict-free LDS.64). No prep_a kernel, no A ldmatrix.
// B: cp.async + ldmatrix, identical to the validated R3 path.
// ---------------------------------------------------------------------------
#define NST 3
#define ASTRIDE 40                     // floats per A smem row (pad 32->40)
#define ABYTES  (128 * ASTRIDE * 4)    // 20480
#define BBYTES  16384                  // bh 8KB + bl 8KB
#define STAGE   (ABYTES + BBYTES)      // 36864
#define GSMEM   (NST * STAGE)          // 110592

__global__ __launch_bounds__(256, 2)
void gemm_mma(const float* __restrict__ X) {
    extern __shared__ char sm[];
    const uint32_t sbase = smem_u32(sm);
    const int tid  = threadIdx.x;
    const int lane = tid & 31;
    const int warp = tid >> 5;
    const int wm = warp & 3;
    const int wn = warp >> 2;
    const int m0 = blockIdx.y * 128;
    const int n0 = blockIdx.x * 128;

    // --- A cp.async mapping: thread -> (row = tid>>1, 64B half = tid&1)
    const int ar  = tid >> 1;
    const int ac0 = (tid & 1) * 4;             // starting 16B chunk (of 8)
    const float* asrc0 = X + (size_t)(m0 + ar) * II + ac0 * 4;
    const uint32_t adst0 = sbase + (uint32_t)(ar * ASTRIDE * 4 + ac0 * 16);

    // --- B cp.async mapping: 128 threads per matrix, one 64B row each
    const int bsel    = tid >> 7;
    const int brow_ld = tid & 127;
    const __half* bsrc = (bsel ? g_bl : g_bh) + (size_t)(n0 + brow_ld) * II;
    const uint32_t bdst = sbase + (uint32_t)(ABYTES + bsel * 8192 + brow_ld * 64);
    const int bxor = (brow_ld >> 1) & 3;

    auto issue = [&](int it) {
        const uint32_t stoff = (uint32_t)(it % NST) * STAGE;
        const float* as = asrc0 + it * 32;
        #pragma unroll
        for (int c = 0; c < 4; c++)
            cp16(adst0 + stoff + c * 16, as + c * 4);
        const __half* bs = bsrc + it * 32;
        #pragma unroll
        for (int ch = 0; ch < 4; ch++)
            cp16(bdst + stoff + (uint32_t)((ch ^ bxor) * 16), bs + ch * 8);
        asm volatile("cp.async.commit_group;");
    };

    issue(0);
    issue(1);

    // --- A fragment smem coordinates
    const int arow0 = wm * 32 + (lane >> 2);   // + mi*16 + (j&1)*8
    const int acol0 = (lane & 3) * 2;          // + kk*16 + (j>>1)*8

    // --- B ldmatrix addressing (R3-proven)
    const int brow = wn * 64 + ((lane >> 4) << 3) + (lane & 7);
    const int bch  = (lane >> 3) & 1;

    float acc[2][8][4];
    #pragma unroll
    for (int i = 0; i < 2; i++)
        #pragma unroll
        for (int j = 0; j < 8; j++)
            #pragma unroll
            for (int q = 0; q < 4; q++) acc[i][j][q] = 0.0f;

    for (int it = 0; it < 16; it++) {
        asm volatile("cp.async.wait_group %0;" :: "n"(1));
        __syncthreads();
        if (it + 2 < 16) issue(it + 2);
        else             asm volatile("cp.async.commit_group;");

        const uint32_t stoff = (uint32_t)(it % NST) * STAGE;
        const float*  As32 = (const float*)(sm + stoff);
        const uint32_t Bs  = sbase + stoff + ABYTES;

        #pragma unroll
        for (int kk = 0; kk < 2; kk++) {
            // A fragments: fp32 smem -> hi/lo fp16 in registers
            uint32_t ah[2][4], al[2][4];
            #pragma unroll
            for (int mi = 0; mi < 2; mi++) {
                #pragma unroll
                for (int j = 0; j < 4; j++) {
                    const int row = arow0 + mi * 16 + (j & 1) * 8;
                    const int col = acol0 + kk * 16 + (j >> 1) * 8;
                    const float2 f = *(const float2*)(As32 + row * ASTRIDE + col);
                    __half2 h  = __float22half2_rn(f);
                    float2  hf = __half22float2(h);
                    __half2 l  = __floats2half2_rn(f.x - hf.x, f.y - hf.y);
                    ah[mi][j] = h2bits(h);
                    al[mi][j] = h2bits(l);
                }
            }

            uint32_t b[4][4];
            // bh: (ah.bh) and (al.bh)
            #pragma unroll
            for (int g = 0; g < 4; g++) {
                const int row = brow + g * 16;
                ldsm_x4(b[g], Bs + row * 64 + (((kk * 2 + bch) ^ ((row >> 1) & 3)) * 16));
            }
            #pragma unroll
            for (int mi = 0; mi < 2; mi++)
                #pragma unroll
                for (int nj = 0; nj < 8; nj++)
                    mma16816(acc[mi][nj], ah[mi], b[nj >> 1][(nj & 1) * 2],
                             b[nj >> 1][(nj & 1) * 2 + 1]);
            #pragma unroll
            for (int mi = 0; mi < 2; mi++)
                #pragma unroll
                for (int nj = 0; nj < 8; nj++)
                    mma16816(acc[mi][nj], al[mi], b[nj >> 1][(nj & 1) * 2],
                             b[nj >> 1][(nj & 1) * 2 + 1]);
            // bl: (ah.bl)
            #pragma unroll
            for (int g = 0; g < 4; g++) {
                const int row = brow + g * 16;
                ldsm_x4(b[g], Bs + 8192 + row * 64 + (((kk * 2 + bch) ^ ((row >> 1) & 3)) * 16));
            }
            #pragma unroll
            for (int mi = 0; mi < 2; mi++)
                #pragma unroll
                for (int nj = 0; nj < 8; nj++)
                    mma16816(acc[mi][nj], ah[mi], b[nj >> 1][(nj & 1) * 2],
                             b[nj >> 1][(nj & 1) * 2 + 1]);
        }
    }

    // Epilogue: undo 2048 scale, store fp32
    const float inv = 1.0f / 2048.0f;
    #pragma unroll
    for (int mi = 0; mi < 2; mi++) {
        const int rr = m0 + wm * 32 + mi * 16 + (lane >> 2);
        #pragma unroll
        for (int nj = 0; nj < 8; nj++) {
            const int cc = n0 + wn * 64 + nj * 8 + 2 * (lane & 3);
            float* p0 = g_wx + (size_t)rr * HH + cc;
            float* p1 = g_wx + (size_t)(rr + 8) * HH + cc;
            *(float2*)p0 = make_float2(acc[mi][nj][0] * inv, acc[mi][nj][1] * inv);
            *(float2*)p1 = make_float2(acc[mi][nj][2] * inv, acc[mi][nj][3] * inv);
        }
    }
}

// ---------------------------------------------------------------------------
// LIF scan v2: producer/consumer smem pipeline.
// 1024 CTAs x 128 threads. CTA owns (b, 32 h-lanes). All threads cp.async
// 64t x 32h fp32 chunks into a 3-stage ring; warp 0 (32 scanners, one per h)
// runs the recurrence from smem and stores spikes coalesced.
// ---------------------------------------------------------------------------
#define SC_TC   64                      // t-steps per chunk
#define SC_NH   32                      // h-lanes per CTA
#define SC_CHB  (SC_TC * SC_NH * 4)     // 8192 bytes per stage

__global__ __launch_bounds__(128)
void lif_scan(const float* __restrict__ alpha,
              const float* __restrict__ u0,
              const float* __restrict__ s0,
              float* __restrict__ out) {
    __shared__ float ws[3][SC_TC][SC_NH];   // 24 KB
    const uint32_t sbase = smem_u32(ws);
    const int tid = threadIdx.x;
    const int b   = blockIdx.x >> 4;
    const int h0  = (blockIdx.x & 15) * SC_NH;

    const float* src = g_wx + (size_t)b * TT * HH + h0;

    // loader mapping: row = tid>>1 (t within chunk), 4 cp16 each
    const int lr  = tid >> 1;
    const int lc0 = (tid & 1) * 4;          // starting 16B chunk (of 8 per row)
    const float* lsrc0 = src + (size_t)lr * HH + lc0 * 4;
    const uint32_t ldst0 = sbase + (uint32_t)(lr * SC_NH * 4 + lc0 * 16);

    auto issue = [&](int c) {
        const uint32_t stoff = (uint32_t)(c % 3) * SC_CHB;
        const float* s = lsrc0 + (size_t)(c * SC_TC) * HH;
        #pragma unroll
        for (int i = 0; i < 4; i++)
            cp16(ldst0 + stoff + i * 16, s + i * 4);
        asm volatile("cp.async.commit_group;");
    };

    issue(0);
    issue(1);

    // scanner state (warp 0 only)
    float u = 0.0f, s = 0.0f, al = 0.0f, ial = 0.0f;
    float* q = out;
    if (tid < SC_NH) {
        const int h = h0 + tid;
        al = alpha[h];
        al = fminf(fmaxf(al, ALPHA_LO), ALPHA_HI);
        ial = 1.0f - al;
        u = u0[b * HH + h];
        s = s0[b * HH + h];
        q = out + (size_t)b * TT * HH + h;
    }

    for (int c = 0; c < TT / SC_TC; c++) {
        asm volatile("cp.async.wait_group %0;" :: "n"(1));
        __syncthreads();
        if (c + 2 < TT / SC_TC) issue(c + 2);
        else                    asm volatile("cp.async.commit_group;");

        if (tid < SC_NH) {
            const int st = c % 3;
            const size_t tb = (size_t)(c * SC_TC) * HH;
            #pragma unroll 1
            for (int t8 = 0; t8 < SC_TC; t8 += 8) {
                float w[8];
                #pragma unroll
                for (int j = 0; j < 8; j++) w[j] = ws[st][t8 + j][tid];
                #pragma unroll
                for (int j = 0; j < 8; j++) {
                    u = fmaf(al, u - s, ial * w[j]);
                    s = (u - 1.0f > 0.0f) ? 1.0f : 0.0f;
                    q[tb + (size_t)(t8 + j) * HH] = s;
                }
            }
        }
        __syncthreads();
    }
}

// ---------------------------------------------------------------------------
extern "C" void kernel_launch(void* const* d_in, const int* in_sizes, int n_in,
                              void* d_out, int out_size) {
    const float* x     = (const float*)d_in[0];  // [B,T,I]
    const float* W     = (const float*)d_in[1];  // [H,I]
    const float* alpha = (const float*)d_in[2];  // [H]
    const float* u0    = (const float*)d_in[3];  // [B,H]
    const float* s0    = (const float*)d_in[4];  // [B,H]
    float* out = (float*)d_out;                  // [B,T,H]

    cudaFuncSetAttribute(gemm_mma, cudaFuncAttributeMaxDynamicSharedMemorySize, GSMEM);

    prep_b<<<(int)(((size_t)HH * II) / 4 / 256), 256>>>(W);

    dim3 grid(HH / 128, MM / 128);               // (4, 512) = 2048 CTAs
    gemm_mma<<<grid, 256, GSMEM>>>(x);

    lif_scan<<<BB * (HH / SC_NH), 128>>>(alpha, u0, s0, out);
}